// round 5
// baseline (speedup 1.0000x reference)
#include <cuda_runtime.h>

#define DIM 256
#define PLANE (DIM*DIM)
#define NELEM (DIM*DIM*DIM)

#define HTILES 64          // h tiles of 4 rows
#define DCHUNKS 16
#define DPC 16             // 16*16 = 256 >= 254
#define NBLOCKS (HTILES*DCHUNKS)   // 1024

__device__ float g_partials[NBLOCKS];
__device__ unsigned int g_count = 0;   // wraps to 0 each launch via atomicInc

__device__ __forceinline__ float sqrt_approx(float x) {
    float r;
    asm("sqrt.approx.f32 %0, %1;" : "=f"(r) : "f"(x));
    return r;
}

__global__ __launch_bounds__(256, 5)
void grad_loss_fused(const float* __restrict__ x1,
                     const float* __restrict__ x2,
                     float* __restrict__ out) {
    __shared__ float ssum[8];
    __shared__ int s_last;

    const int tx = threadIdx.x;            // 0..63 -> w quad
    const int ty = threadIdx.y;            // 0..3  -> h row
    const int htile = blockIdx.x;          // 0..63
    const int chunk = blockIdx.y;          // 0..15
    const int bid = chunk * HTILES + htile;

    const int h  = 1 + htile * 4 + ty;     // 1..256
    const int w0 = tx * 4;
    const int d0 = 1 + chunk * DPC;
    const int d1 = min(DIM - 2, d0 + DPC - 1);

    const bool hcomp = (h <= DIM - 2);     // uniform per warp

    float local = 0.0f;

    if (hcomp) {
        const float wh  = (h == 1 || h == DIM - 2) ? 2.0f : 1.0f;
        const float wl  = (tx == 0)  ? 2.0f : 1.0f;
        const float wr  = (tx == 63) ? 2.0f : 1.0f;
        const bool  hasl = (tx > 0);
        const bool  hasr = (tx < 63);

        const float* p1 = x1 + h * DIM + w0;
        const float* p2 = x2 + h * DIM + w0;

        // Register window: B = plane d, C = plane d+1. D = plane d+2 is
        // prefetched one full iteration before use. A = plane d-1 comes
        // from cache (loaded by this thread 3 iterations earlier).
        float4 B0 = *(const float4*)(p1 + d0 * PLANE);
        float4 B1 = *(const float4*)(p2 + d0 * PLANE);
        float4 C0 = *(const float4*)(p1 + (d0 + 1) * PLANE);
        float4 C1 = *(const float4*)(p2 + (d0 + 1) * PLANE);

        #pragma unroll 2
        for (int d = d0; d <= d1; ++d) {
            const float* q1 = p1 + d * PLANE;
            const float* q2 = p2 + d * PLANE;

            // ---- prefetch plane d+2 (consumed NEXT iteration) ----
            const int dp = min(d + 2, DIM - 1);
            const float4 D0 = *(const float4*)(p1 + dp * PLANE);
            const float4 D1 = *(const float4*)(p2 + dp * PLANE);

            // ---- cache-resident loads for this iteration ----
            const float4 A0  = *(const float4*)(q1 - PLANE);
            const float4 A1  = *(const float4*)(q2 - PLANE);
            const float4 up0 = *(const float4*)(q1 - DIM);
            const float4 dn0 = *(const float4*)(q1 + DIM);
            const float4 up1 = *(const float4*)(q2 - DIM);
            const float4 dn1 = *(const float4*)(q2 + DIM);
            const float lf0 = hasl ? q1[-1] : 0.0f;
            const float rt0 = hasr ? q1[4]  : 0.0f;
            const float lf1 = hasl ? q2[-1] : 0.0f;
            const float rt1 = hasr ? q2[4]  : 0.0f;

            const float wd = (d == 1 || d == DIM - 2) ? 2.0f : 1.0f;

            float gw, gh, gd;
            float m00, m01, m02, m03;
            gw = B0.y - lf0;  gh = dn0.x - up0.x;  gd = C0.x - A0.x;
            m00 = sqrt_approx(gw*gw + gh*gh + gd*gd + 1e-6f);
            gw = B0.z - B0.x; gh = dn0.y - up0.y;  gd = C0.y - A0.y;
            m01 = sqrt_approx(gw*gw + gh*gh + gd*gd + 1e-6f);
            gw = B0.w - B0.y; gh = dn0.z - up0.z;  gd = C0.z - A0.z;
            m02 = sqrt_approx(gw*gw + gh*gh + gd*gd + 1e-6f);
            gw = rt0 - B0.z;  gh = dn0.w - up0.w;  gd = C0.w - A0.w;
            m03 = sqrt_approx(gw*gw + gh*gh + gd*gd + 1e-6f);

            float m10, m11, m12, m13;
            gw = B1.y - lf1;  gh = dn1.x - up1.x;  gd = C1.x - A1.x;
            m10 = sqrt_approx(gw*gw + gh*gh + gd*gd + 1e-6f);
            gw = B1.z - B1.x; gh = dn1.y - up1.y;  gd = C1.y - A1.y;
            m11 = sqrt_approx(gw*gw + gh*gh + gd*gd + 1e-6f);
            gw = B1.w - B1.y; gh = dn1.z - up1.z;  gd = C1.z - A1.z;
            m12 = sqrt_approx(gw*gw + gh*gh + gd*gd + 1e-6f);
            gw = rt1 - B1.z;  gh = dn1.w - up1.w;  gd = C1.w - A1.w;
            m13 = sqrt_approx(gw*gw + gh*gh + gd*gd + 1e-6f);

            float s = 0.0f;
            if (hasl) s += fabsf(m00 - m10);
            s += wl * fabsf(m01 - m11);
            s += wr * fabsf(m02 - m12);
            if (hasr) s += fabsf(m03 - m13);
            local += wd * wh * s;

            // rotate window forward
            B0 = C0; B1 = C1; C0 = D0; C1 = D1;
        }
    }

    // ---- block reduction ----
    #pragma unroll
    for (int off = 16; off > 0; off >>= 1)
        local += __shfl_xor_sync(0xffffffffu, local, off);

    const int tid  = ty * 64 + tx;
    const int warp = tid >> 5;
    const int lane = tid & 31;
    if (lane == 0) ssum[warp] = local;
    __syncthreads();

    if (tid == 0) {
        float v = 0.0f;
        #pragma unroll
        for (int i = 0; i < 8; ++i) v += ssum[i];
        g_partials[bid] = v;
        __threadfence();
        unsigned int t = atomicInc(&g_count, NBLOCKS - 1);
        s_last = (t == NBLOCKS - 1);
    }
    __syncthreads();

    // ---- last block finishes the global reduction ----
    if (s_last) {
        __threadfence();
        float s = 0.0f;
        const volatile float* gp = g_partials;
        for (int i = tid; i < NBLOCKS; i += 256)
            s += gp[i];
        #pragma unroll
        for (int off = 16; off > 0; off >>= 1)
            s += __shfl_xor_sync(0xffffffffu, s, off);
        if (lane == 0) ssum[warp] = s;
        __syncthreads();
        if (warp == 0) {
            float v = (lane < 8) ? ssum[lane] : 0.0f;
            #pragma unroll
            for (int off = 4; off > 0; off >>= 1)
                v += __shfl_xor_sync(0xffffffffu, v, off);
            if (lane == 0)
                out[0] = v * (1.0f / (float)NELEM);
        }
    }
}

extern "C" void kernel_launch(void* const* d_in, const int* in_sizes, int n_in,
                              void* d_out, int out_size) {
    const float* x1 = (const float*)d_in[0];
    const float* x2 = (const float*)d_in[1];
    float* out = (float*)d_out;
    (void)in_sizes; (void)n_in; (void)out_size;

    dim3 block(64, 4, 1);
    dim3 grid(HTILES, DCHUNKS, 1);
    grad_loss_fused<<<grid, block>>>(x1, x2, out);
}

// round 6
// speedup vs baseline: 1.7653x; 1.7653x over previous
#include <cuda_runtime.h>

#define DIM 256
#define PLANE (DIM*DIM)
#define NELEM (DIM*DIM*DIM)

#define HTILES 64          // h tiles of 4 rows
#define DCHUNKS 16
#define DPC 16             // 16*16 = 256 >= 254
#define NBLOCKS (HTILES*DCHUNKS)   // 1024

__device__ float g_partials[NBLOCKS];
__device__ unsigned int g_count = 0;   // wraps to 0 each launch via atomicInc

__device__ __forceinline__ float sqrt_approx(float x) {
    float r;
    asm("sqrt.approx.f32 %0, %1;" : "=f"(r) : "f"(x));
    return r;
}

__global__ __launch_bounds__(256, 4)
void grad_loss_fused(const float* __restrict__ x1,
                     const float* __restrict__ x2,
                     float* __restrict__ out) {
    __shared__ float ssum[8];
    __shared__ int s_last;

    const int tx = threadIdx.x;            // 0..63 -> w quad
    const int ty = threadIdx.y;            // 0..3  -> h row
    const int htile = blockIdx.x;          // 0..63
    const int chunk = blockIdx.y;          // 0..15
    const int bid = chunk * HTILES + htile;

    const int h  = 1 + htile * 4 + ty;     // 1..256
    const int w0 = tx * 4;
    const int d0 = 1 + chunk * DPC;
    const int niter = min(DIM - 2, d0 + DPC - 1) - d0 + 1;

    const bool hcomp = (h <= DIM - 2);     // uniform per warp

    float local = 0.0f;

    if (hcomp) {
        const float wh  = (h == 1 || h == DIM - 2) ? 2.0f : 1.0f;
        const float wl  = (tx == 0)  ? 2.0f : 1.0f;
        const float wr  = (tx == 63) ? 2.0f : 1.0f;
        const bool  hasl = (tx > 0);
        const bool  hasr = (tx < 63);

        // q points at (d, h, w0); advance by PLANE per iteration.
        const float* q1 = x1 + d0 * PLANE + h * DIM + w0;
        const float* q2 = x2 + d0 * PLANE + h * DIM + w0;

        // Register window: B = plane d, C = plane d+1. D = plane d+2
        // prefetched one iteration ahead; A = plane d-1 re-read from cache.
        float4 B0 = *(const float4*)(q1);
        float4 B1 = *(const float4*)(q2);
        float4 C0 = *(const float4*)(q1 + PLANE);
        float4 C1 = *(const float4*)(q2 + PLANE);

        int d = d0;
        #pragma unroll 2
        for (int it = 0; it < niter; ++it, ++d, q1 += PLANE, q2 += PLANE) {
            // ---- prefetch plane d+2 (consumed NEXT iteration) ----
            const int pf = (d + 2 <= DIM - 1) ? 2 * PLANE : PLANE;
            const float4 D0 = *(const float4*)(q1 + pf);
            const float4 D1 = *(const float4*)(q2 + pf);

            // ---- cache-resident loads for this iteration ----
            const float4 A0  = *(const float4*)(q1 - PLANE);
            const float4 A1  = *(const float4*)(q2 - PLANE);
            const float4 up0 = *(const float4*)(q1 - DIM);
            const float4 dn0 = *(const float4*)(q1 + DIM);
            const float4 up1 = *(const float4*)(q2 - DIM);
            const float4 dn1 = *(const float4*)(q2 + DIM);
            const float lf0 = hasl ? q1[-1] : 0.0f;
            const float rt0 = hasr ? q1[4]  : 0.0f;
            const float lf1 = hasl ? q2[-1] : 0.0f;
            const float rt1 = hasr ? q2[4]  : 0.0f;

            const float wd = (d == 1 || d == DIM - 2) ? 2.0f : 1.0f;

            float gw, gh, gd;
            float m00, m01, m02, m03;
            gw = B0.y - lf0;  gh = dn0.x - up0.x;  gd = C0.x - A0.x;
            m00 = sqrt_approx(gw*gw + gh*gh + gd*gd + 1e-6f);
            gw = B0.z - B0.x; gh = dn0.y - up0.y;  gd = C0.y - A0.y;
            m01 = sqrt_approx(gw*gw + gh*gh + gd*gd + 1e-6f);
            gw = B0.w - B0.y; gh = dn0.z - up0.z;  gd = C0.z - A0.z;
            m02 = sqrt_approx(gw*gw + gh*gh + gd*gd + 1e-6f);
            gw = rt0 - B0.z;  gh = dn0.w - up0.w;  gd = C0.w - A0.w;
            m03 = sqrt_approx(gw*gw + gh*gh + gd*gd + 1e-6f);

            float m10, m11, m12, m13;
            gw = B1.y - lf1;  gh = dn1.x - up1.x;  gd = C1.x - A1.x;
            m10 = sqrt_approx(gw*gw + gh*gh + gd*gd + 1e-6f);
            gw = B1.z - B1.x; gh = dn1.y - up1.y;  gd = C1.y - A1.y;
            m11 = sqrt_approx(gw*gw + gh*gh + gd*gd + 1e-6f);
            gw = B1.w - B1.y; gh = dn1.z - up1.z;  gd = C1.z - A1.z;
            m12 = sqrt_approx(gw*gw + gh*gh + gd*gd + 1e-6f);
            gw = rt1 - B1.z;  gh = dn1.w - up1.w;  gd = C1.w - A1.w;
            m13 = sqrt_approx(gw*gw + gh*gh + gd*gd + 1e-6f);

            float s = 0.0f;
            if (hasl) s += fabsf(m00 - m10);
            s += wl * fabsf(m01 - m11);
            s += wr * fabsf(m02 - m12);
            if (hasr) s += fabsf(m03 - m13);
            local += wd * wh * s;

            // rotate window forward
            B0 = C0; B1 = C1; C0 = D0; C1 = D1;
        }
    }

    // ---- block reduction ----
    #pragma unroll
    for (int off = 16; off > 0; off >>= 1)
        local += __shfl_xor_sync(0xffffffffu, local, off);

    const int tid  = ty * 64 + tx;
    const int warp = tid >> 5;
    const int lane = tid & 31;
    if (lane == 0) ssum[warp] = local;
    __syncthreads();

    if (tid == 0) {
        float v = 0.0f;
        #pragma unroll
        for (int i = 0; i < 8; ++i) v += ssum[i];
        g_partials[bid] = v;
        __threadfence();
        unsigned int t = atomicInc(&g_count, NBLOCKS - 1);
        s_last = (t == NBLOCKS - 1);
    }
    __syncthreads();

    // ---- last block finishes the global reduction ----
    if (s_last) {
        __threadfence();
        float s = 0.0f;
        const volatile float* gp = g_partials;
        for (int i = tid; i < NBLOCKS; i += 256)
            s += gp[i];
        #pragma unroll
        for (int off = 16; off > 0; off >>= 1)
            s += __shfl_xor_sync(0xffffffffu, s, off);
        if (lane == 0) ssum[warp] = s;
        __syncthreads();
        if (warp == 0) {
            float v = (lane < 8) ? ssum[lane] : 0.0f;
            #pragma unroll
            for (int off = 4; off > 0; off >>= 1)
                v += __shfl_xor_sync(0xffffffffu, v, off);
            if (lane == 0)
                out[0] = v * (1.0f / (float)NELEM);
        }
    }
}

extern "C" void kernel_launch(void* const* d_in, const int* in_sizes, int n_in,
                              void* d_out, int out_size) {
    const float* x1 = (const float*)d_in[0];
    const float* x2 = (const float*)d_in[1];
    float* out = (float*)d_out;
    (void)in_sizes; (void)n_in; (void)out_size;

    dim3 block(64, 4, 1);
    dim3 grid(HTILES, DCHUNKS, 1);
    grad_loss_fused<<<grid, block>>>(x1, x2, out);
}